// round 1
// baseline (speedup 1.0000x reference)
#include <cuda_runtime.h>
#include <math.h>

// Problem constants
#define HIDDEN 2048
#define FFN    5632
#define NE     8
#define T_TOK  4096          // BATCH * SEQ
#define NCODE  (T_TOK * 2)   // token*2 + k  (top-2)

// ---- scratch (no allocations allowed; __device__ globals) ----
__device__ float g_hbuf[8192ULL * 5632ULL];   // silu(g)*u per selected (token,k) row  [~184MB]
__device__ float g_ybuf[8192ULL * 2048ULL];   // expert output per (token,k) row       [~64MB]
__device__ float g_wbuf[NCODE];               // routing weight per code
__device__ int   g_counts[NE];
__device__ int   g_elist[NE * T_TOK];         // per-expert list of codes

// ============================================================
// 0) zero expert counts
// ============================================================
__global__ void zero_counts_kernel() {
    if (threadIdx.x < NE) g_counts[threadIdx.x] = 0;
}

// ============================================================
// 1) router: logits -> top2 -> softmax -> bucket (token,k) by expert
// ============================================================
__global__ __launch_bounds__(256) void router_kernel(
    const float* __restrict__ x, const float* __restrict__ gw)
{
    const int t   = blockIdx.x;
    const int tid = threadIdx.x;
    const float* xr = x + (size_t)t * HIDDEN;

    float acc[NE];
#pragma unroll
    for (int e = 0; e < NE; e++) acc[e] = 0.f;

    for (int d = tid; d < HIDDEN; d += 256) {
        float xv = xr[d];
#pragma unroll
        for (int e = 0; e < NE; e++)
            acc[e] = fmaf(xv, gw[e * HIDDEN + d], acc[e]);
    }
    // warp reduce
#pragma unroll
    for (int e = 0; e < NE; e++) {
#pragma unroll
        for (int off = 16; off > 0; off >>= 1)
            acc[e] += __shfl_down_sync(0xffffffffu, acc[e], off);
    }
    __shared__ float red[NE][8];
    const int w = tid >> 5, lane = tid & 31;
    if (lane == 0) {
#pragma unroll
        for (int e = 0; e < NE; e++) red[e][w] = acc[e];
    }
    __syncthreads();

    if (tid == 0) {
        float logit[NE];
#pragma unroll
        for (int e = 0; e < NE; e++) {
            float s = 0.f;
#pragma unroll
            for (int ww = 0; ww < 8; ww++) s += red[e][ww];
            logit[e] = s;
        }
        // top-2, lowest-index wins ties (jax.lax.top_k semantics)
        int i0 = 0; float v0 = logit[0];
#pragma unroll
        for (int e = 1; e < NE; e++)
            if (logit[e] > v0) { v0 = logit[e]; i0 = e; }
        int i1 = -1; float v1 = -1e30f;
#pragma unroll
        for (int e = 0; e < NE; e++)
            if (e != i0 && logit[e] > v1) { v1 = logit[e]; i1 = e; }

        // softmax over [v0, v1] (v0 is the max)
        float e1 = expf(v1 - v0);
        float w0 = 1.f / (1.f + e1);
        float w1 = e1 * w0;

        int s0 = atomicAdd(&g_counts[i0], 1);
        g_elist[i0 * T_TOK + s0] = t * 2;
        int s1 = atomicAdd(&g_counts[i1], 1);
        g_elist[i1 * T_TOK + s1] = t * 2 + 1;
        g_wbuf[t * 2]     = w0;
        g_wbuf[t * 2 + 1] = w1;
    }
}

// ============================================================
// 2) GEMM1: for each expert, gathered rows of x -> h = silu(x.Wg^T) * (x.Wu^T)
//    tile: BM=128 (rows), BN=64 (ffn cols), BK=16; 256 thr, 8x4 microtile
// ============================================================
#define BM 128
#define BN 64
#define BK 16

__global__ __launch_bounds__(256) void gemm1_kernel(
    const float* __restrict__ x,
    const float* __restrict__ wg,
    const float* __restrict__ wu)
{
    const int e   = blockIdx.z;
    const int cnt = g_counts[e];
    const int m0  = blockIdx.y * BM;
    if (m0 >= cnt) return;
    const int n0  = blockIdx.x * BN;
    const int tid = threadIdx.x;

    __shared__ __align__(16) float sx[BK][BM];
    __shared__ __align__(16) float sg[BK][BN];
    __shared__ __align__(16) float su[BK][BN];
    __shared__ int scode[BM];
    __shared__ int stok[BM];

    if (tid < BM) {
        int slot = m0 + tid;
        int c = (slot < cnt) ? g_elist[e * T_TOK + slot] : -1;
        scode[tid] = c;
        stok[tid]  = (c < 0) ? 0 : (c >> 1);
    }
    __syncthreads();

    float accg[8][4], accu[8][4];
#pragma unroll
    for (int i = 0; i < 8; i++)
#pragma unroll
        for (int j = 0; j < 4; j++) { accg[i][j] = 0.f; accu[i][j] = 0.f; }

    const int tx = tid & 15;        // n group
    const int ty = tid >> 4;        // m group
    const int lm = tid >> 1;        // x-load row     0..127
    const int lk = (tid & 1) * 8;   // x-load k chunk 0 or 8
    const int wn = tid >> 2;        // w-load row     0..63
    const int wk = (tid & 3) * 4;   // w-load k chunk 0..12

    const float* wg_e = wg + (size_t)e * FFN * HIDDEN;
    const float* wu_e = wu + (size_t)e * FFN * HIDDEN;

    for (int k0 = 0; k0 < HIDDEN; k0 += BK) {
        {   // gathered x tile
            const float* src = x + (size_t)stok[lm] * HIDDEN + k0 + lk;
            float4 a = *(const float4*)src;
            float4 b = *(const float4*)(src + 4);
            sx[lk + 0][lm] = a.x; sx[lk + 1][lm] = a.y;
            sx[lk + 2][lm] = a.z; sx[lk + 3][lm] = a.w;
            sx[lk + 4][lm] = b.x; sx[lk + 5][lm] = b.y;
            sx[lk + 6][lm] = b.z; sx[lk + 7][lm] = b.w;
        }
        {   // weight tiles
            const float* srcg = wg_e + (size_t)(n0 + wn) * HIDDEN + k0 + wk;
            float4 a = *(const float4*)srcg;
            sg[wk + 0][wn] = a.x; sg[wk + 1][wn] = a.y;
            sg[wk + 2][wn] = a.z; sg[wk + 3][wn] = a.w;
            const float* srcu = wu_e + (size_t)(n0 + wn) * HIDDEN + k0 + wk;
            float4 b = *(const float4*)srcu;
            su[wk + 0][wn] = b.x; su[wk + 1][wn] = b.y;
            su[wk + 2][wn] = b.z; su[wk + 3][wn] = b.w;
        }
        __syncthreads();

#pragma unroll
        for (int kk = 0; kk < BK; kk++) {
            float4 xa = *(const float4*)(&sx[kk][ty * 8]);
            float4 xb = *(const float4*)(&sx[kk][ty * 8 + 4]);
            float4 gv = *(const float4*)(&sg[kk][tx * 4]);
            float4 uv = *(const float4*)(&su[kk][tx * 4]);
            float xv[8] = {xa.x, xa.y, xa.z, xa.w, xb.x, xb.y, xb.z, xb.w};
            float gg[4] = {gv.x, gv.y, gv.z, gv.w};
            float uu[4] = {uv.x, uv.y, uv.z, uv.w};
#pragma unroll
            for (int i = 0; i < 8; i++)
#pragma unroll
                for (int j = 0; j < 4; j++) {
                    accg[i][j] = fmaf(xv[i], gg[j], accg[i][j]);
                    accu[i][j] = fmaf(xv[i], uu[j], accu[i][j]);
                }
        }
        __syncthreads();
    }

    // epilogue: h = silu(g) * u  -> g_hbuf[code][n]
#pragma unroll
    for (int i = 0; i < 8; i++) {
        int m = ty * 8 + i;
        int c = scode[m];
        if (c < 0) continue;
        float4 hv;
        float g0 = accg[i][0], g1 = accg[i][1], g2 = accg[i][2], g3 = accg[i][3];
        hv.x = g0 / (1.f + expf(-g0)) * accu[i][0];
        hv.y = g1 / (1.f + expf(-g1)) * accu[i][1];
        hv.z = g2 / (1.f + expf(-g2)) * accu[i][2];
        hv.w = g3 / (1.f + expf(-g3)) * accu[i][3];
        *(float4*)&g_hbuf[(size_t)c * FFN + n0 + tx * 4] = hv;
    }
}

// ============================================================
// 3) GEMM2: y[code][d] = h[code] . w_out[e][d][:]   (K = FFN)
// ============================================================
__global__ __launch_bounds__(256) void gemm2_kernel(
    const float* __restrict__ wout)
{
    const int e   = blockIdx.z;
    const int cnt = g_counts[e];
    const int m0  = blockIdx.y * BM;
    if (m0 >= cnt) return;
    const int n0  = blockIdx.x * BN;
    const int tid = threadIdx.x;

    __shared__ __align__(16) float sh[BK][BM];
    __shared__ __align__(16) float sw[BK][BN];
    __shared__ int scode[BM];

    if (tid < BM) {
        int slot = m0 + tid;
        scode[tid] = (slot < cnt) ? g_elist[e * T_TOK + slot] : -1;
    }
    __syncthreads();

    float acc[8][4];
#pragma unroll
    for (int i = 0; i < 8; i++)
#pragma unroll
        for (int j = 0; j < 4; j++) acc[i][j] = 0.f;

    const int tx = tid & 15;
    const int ty = tid >> 4;
    const int lm = tid >> 1;
    const int lk = (tid & 1) * 8;
    const int wn = tid >> 2;
    const int wk = (tid & 3) * 4;

    const float* wout_e = wout + (size_t)e * HIDDEN * FFN;
    const int hrow = (scode[lm] < 0) ? 0 : scode[lm];

    for (int k0 = 0; k0 < FFN; k0 += BK) {
        {
            const float* src = g_hbuf + (size_t)hrow * FFN + k0 + lk;
            float4 a = *(const float4*)src;
            float4 b = *(const float4*)(src + 4);
            sh[lk + 0][lm] = a.x; sh[lk + 1][lm] = a.y;
            sh[lk + 2][lm] = a.z; sh[lk + 3][lm] = a.w;
            sh[lk + 4][lm] = b.x; sh[lk + 5][lm] = b.y;
            sh[lk + 6][lm] = b.z; sh[lk + 7][lm] = b.w;
        }
        {
            const float* srcw = wout_e + (size_t)(n0 + wn) * FFN + k0 + wk;
            float4 a = *(const float4*)srcw;
            sw[wk + 0][wn] = a.x; sw[wk + 1][wn] = a.y;
            sw[wk + 2][wn] = a.z; sw[wk + 3][wn] = a.w;
        }
        __syncthreads();

#pragma unroll
        for (int kk = 0; kk < BK; kk++) {
            float4 xa = *(const float4*)(&sh[kk][ty * 8]);
            float4 xb = *(const float4*)(&sh[kk][ty * 8 + 4]);
            float4 wv = *(const float4*)(&sw[kk][tx * 4]);
            float xv[8] = {xa.x, xa.y, xa.z, xa.w, xb.x, xb.y, xb.z, xb.w};
            float ww[4] = {wv.x, wv.y, wv.z, wv.w};
#pragma unroll
            for (int i = 0; i < 8; i++)
#pragma unroll
                for (int j = 0; j < 4; j++)
                    acc[i][j] = fmaf(xv[i], ww[j], acc[i][j]);
        }
        __syncthreads();
    }

#pragma unroll
    for (int i = 0; i < 8; i++) {
        int m = ty * 8 + i;
        int c = scode[m];
        if (c < 0) continue;
        float4 yv = make_float4(acc[i][0], acc[i][1], acc[i][2], acc[i][3]);
        *(float4*)&g_ybuf[(size_t)c * HIDDEN + n0 + tx * 4] = yv;
    }
}

// ============================================================
// 4) combine: out[t] = bias + w0*y[2t] + w1*y[2t+1]  (deterministic)
// ============================================================
__global__ __launch_bounds__(256) void combine_kernel(
    const float* __restrict__ bias, float* __restrict__ out)
{
    int i = blockIdx.x * blockDim.x + threadIdx.x;   // float4 index
    const int n4 = (T_TOK * HIDDEN) / 4;
    if (i >= n4) return;
    int elem = i * 4;
    int t = elem / HIDDEN;
    int d = elem % HIDDEN;

    float w0 = g_wbuf[2 * t];
    float w1 = g_wbuf[2 * t + 1];
    float4 y0 = *(const float4*)&g_ybuf[(size_t)(2 * t) * HIDDEN + d];
    float4 y1 = *(const float4*)&g_ybuf[(size_t)(2 * t + 1) * HIDDEN + d];
    float4 b  = *(const float4*)&bias[d];
    float4 o;
    o.x = fmaf(w0, y0.x, fmaf(w1, y1.x, b.x));
    o.y = fmaf(w0, y0.y, fmaf(w1, y1.y, b.y));
    o.z = fmaf(w0, y0.z, fmaf(w1, y1.z, b.z));
    o.w = fmaf(w0, y0.w, fmaf(w1, y1.w, b.w));
    *(float4*)&out[elem] = o;
}

// ============================================================
extern "C" void kernel_launch(void* const* d_in, const int* in_sizes, int n_in,
                              void* d_out, int out_size)
{
    const float* x    = (const float*)d_in[0];   // [4096, 2048]
    const float* gw   = (const float*)d_in[1];   // [8, 2048]
    const float* wg   = (const float*)d_in[2];   // [8, 5632, 2048]
    const float* wu   = (const float*)d_in[3];   // [8, 5632, 2048]
    const float* wout = (const float*)d_in[4];   // [8, 2048, 5632]
    const float* bias = (const float*)d_in[5];   // [2048]
    float* out = (float*)d_out;

    zero_counts_kernel<<<1, 32>>>();
    router_kernel<<<T_TOK, 256>>>(x, gw);

    dim3 g1(FFN / BN, T_TOK / BM, NE);      // (88, 32, 8)
    gemm1_kernel<<<g1, 256>>>(x, wg, wu);

    dim3 g2(HIDDEN / BN, T_TOK / BM, NE);   // (32, 32, 8)
    gemm2_kernel<<<g2, 256>>>(wout);

    int n4 = (T_TOK * HIDDEN) / 4;
    combine_kernel<<<(n4 + 255) / 256, 256>>>(bias, out);
}